// round 1
// baseline (speedup 1.0000x reference)
#include <cuda_runtime.h>

// Problem constants (fixed by the reference)
#define KK   27
#define RR   50000
#define CIN  64
#define COUT 64
#define NOUT 150000

#define TILE 128      // rules per block
#define XPAD 130      // xs row stride in floats (even -> 8B aligned, 130%32=2 -> low conflict)

typedef unsigned long long ull;

// ---- packed f32x2 helpers -------------------------------------------------
__device__ __forceinline__ ull pk2(float lo, float hi) {
    ull r; asm("mov.b64 %0, {%1, %2};" : "=l"(r) : "f"(lo), "f"(hi)); return r;
}
__device__ __forceinline__ void upk2(ull v, float& lo, float& hi) {
    asm("mov.b64 {%0, %1}, %2;" : "=f"(lo), "=f"(hi) : "l"(v));
}
__device__ __forceinline__ ull fma2(ull a, ull b, ull c) {
    ull d; asm("fma.rn.f32x2 %0, %1, %2, %3;" : "=l"(d) : "l"(a), "l"(b), "l"(c)); return d;
}
// vectorized global reduction (PTX ISA 8.1+, sm_90+)
__device__ __forceinline__ void red4(float* p, float a, float b, float c, float d) {
    asm volatile("red.global.add.v4.f32 [%0], {%1, %2, %3, %4};"
                 :: "l"(p), "f"(a), "f"(b), "f"(c), "f"(d) : "memory");
}

// ---- out = bias broadcast --------------------------------------------------
__global__ void init_out_kernel(float4* __restrict__ out4, const float4* __restrict__ bias4) {
    int i = blockIdx.x * blockDim.x + threadIdx.x;
    if (i < NOUT * (COUT / 4)) {
        out4[i] = bias4[i & (COUT / 4 - 1)];
    }
}

// ---- main: per-offset tiled gather -> register GEMM -> red.v4 scatter ------
// smem layout (dynamic):
//   ull   Wd[CIN*COUT]       : W[k] duplicated {w,w}        = 32768 B
//   float xs[CIN*XPAD]       : gathered x, transposed [c][r] = 33280 B
//   int   ism[TILE], osm[TILE]                                = 1024 B
extern "C" __global__ void __launch_bounds__(256, 2)
sparse_conv_kernel(const float* __restrict__ x,
                   const float* __restrict__ w,
                   const int*   __restrict__ in_idx,
                   const int*   __restrict__ out_idx,
                   float*       __restrict__ out)
{
    extern __shared__ char smem_raw[];
    ull*   Wd  = (ull*)smem_raw;
    float* xs  = (float*)(smem_raw + CIN * COUT * sizeof(ull));
    int*   ism = (int*)(smem_raw + CIN * COUT * sizeof(ull) + CIN * XPAD * sizeof(float));
    int*   osm = ism + TILE;

    const int k     = blockIdx.y;
    const int rbase = blockIdx.x * TILE;
    const int nvalid = min(TILE, RR - rbase);
    const int tid   = threadIdx.x;

    // ---- stage W[k], duplicated into f32x2 {w,w} ----
    const float* wk = w + k * CIN * COUT;
    #pragma unroll
    for (int i = tid; i < CIN * COUT; i += 256) {
        float v = wk[i];
        Wd[i] = pk2(v, v);
    }

    // ---- stage rule indices ----
    if (tid < TILE) {
        bool v = tid < nvalid;
        int rr = k * RR + rbase + tid;
        ism[tid] = v ? in_idx[rr]  : -1;
        osm[tid] = v ? out_idx[rr] : -1;
    }
    __syncthreads();

    // ---- gather x rows, transposed: xs[c][r] ----
    const float4* x4 = (const float4*)x;
    #pragma unroll
    for (int i = tid; i < TILE * (CIN / 4); i += 256) {
        int r = i >> 4;          // rule 0..127
        int q = i & 15;          // float4 chunk 0..15
        float4 v = make_float4(0.f, 0.f, 0.f, 0.f);
        int gi = ism[r];
        if (gi >= 0) v = x4[gi * (CIN / 4) + q];
        xs[(q * 4 + 0) * XPAD + r] = v.x;
        xs[(q * 4 + 1) * XPAD + r] = v.y;
        xs[(q * 4 + 2) * XPAD + r] = v.z;
        xs[(q * 4 + 3) * XPAD + r] = v.w;
    }
    __syncthreads();

    // ---- register-blocked GEMM ----
    // warp wp handles 16 rules: half-warp (16 lanes) covers all 64 channels
    // (4 ch/lane), each half handles 8 rules = 4 rule-PAIRS packed in f32x2.
    const int lane = tid & 31;
    const int wp   = tid >> 5;
    const int half = lane >> 4;
    const int hl   = lane & 15;
    const int n0   = hl * 4;              // this thread's 4 output channels
    const int rb   = wp * 16 + half * 8;  // this thread's 8 rules (4 pairs)

    ull acc[4][4];                        // [rule_pair][channel]
    #pragma unroll
    for (int i = 0; i < 4; i++)
        #pragma unroll
        for (int j = 0; j < 4; j++) acc[i][j] = pk2(0.f, 0.f);

    #pragma unroll 4
    for (int c = 0; c < CIN; c++) {
        // x pairs: {x[r0][c], x[r1][c]} — natural LDS.64, broadcast per half
        const ull* xr = (const ull*)(xs + c * XPAD + rb);
        ull xp0 = xr[0], xp1 = xr[1], xp2 = xr[2], xp3 = xr[3];
        // duplicated W: two LDS.128
        const ulonglong2* wr = (const ulonglong2*)(Wd + c * COUT + n0);
        ulonglong2 wa = wr[0], wb = wr[1];

        acc[0][0] = fma2(xp0, wa.x, acc[0][0]);
        acc[0][1] = fma2(xp0, wa.y, acc[0][1]);
        acc[0][2] = fma2(xp0, wb.x, acc[0][2]);
        acc[0][3] = fma2(xp0, wb.y, acc[0][3]);
        acc[1][0] = fma2(xp1, wa.x, acc[1][0]);
        acc[1][1] = fma2(xp1, wa.y, acc[1][1]);
        acc[1][2] = fma2(xp1, wb.x, acc[1][2]);
        acc[1][3] = fma2(xp1, wb.y, acc[1][3]);
        acc[2][0] = fma2(xp2, wa.x, acc[2][0]);
        acc[2][1] = fma2(xp2, wa.y, acc[2][1]);
        acc[2][2] = fma2(xp2, wb.x, acc[2][2]);
        acc[2][3] = fma2(xp2, wb.y, acc[2][3]);
        acc[3][0] = fma2(xp3, wa.x, acc[3][0]);
        acc[3][1] = fma2(xp3, wa.y, acc[3][1]);
        acc[3][2] = fma2(xp3, wb.x, acc[3][2]);
        acc[3][3] = fma2(xp3, wb.y, acc[3][3]);
    }

    // ---- scatter-add: one red.global.add.v4.f32 per rule per thread ----
    #pragma unroll
    for (int rp = 0; rp < 4; rp++) {
        float v0[4], v1[4];
        #pragma unroll
        for (int n = 0; n < 4; n++) {
            upk2(acc[rp][n], v0[n], v1[n]);
        }
        int r0 = rb + 2 * rp;
        int o0 = osm[r0];
        if (o0 >= 0) red4(out + (size_t)o0 * COUT + n0, v0[0], v0[1], v0[2], v0[3]);
        int o1 = osm[r0 + 1];
        if (o1 >= 0) red4(out + (size_t)o1 * COUT + n0, v1[0], v1[1], v1[2], v1[3]);
    }
}

extern "C" void kernel_launch(void* const* d_in, const int* in_sizes, int n_in,
                              void* d_out, int out_size)
{
    const float* x       = (const float*)d_in[0];
    const float* w       = (const float*)d_in[1];
    const float* bias    = (const float*)d_in[2];
    const int*   in_idx  = (const int*)d_in[3];
    const int*   out_idx = (const int*)d_in[4];
    float*       out     = (float*)d_out;

    // 1) out = bias (broadcast); out is poisoned before timing
    {
        int n4 = NOUT * (COUT / 4);
        init_out_kernel<<<(n4 + 255) / 256, 256>>>((float4*)out, (const float4*)bias);
    }

    // 2) tiled gather/GEMM/scatter
    size_t smem = (size_t)CIN * COUT * sizeof(ull)      // 32768
                + (size_t)CIN * XPAD * sizeof(float)    // 33280
                + 2 * TILE * sizeof(int);               // 1024
    cudaFuncSetAttribute(sparse_conv_kernel,
                         cudaFuncAttributeMaxDynamicSharedMemorySize, (int)smem);
    dim3 grid((RR + TILE - 1) / TILE, KK);
    sparse_conv_kernel<<<grid, 256, smem>>>(x, w, in_idx, out_idx, out);
}

// round 2
// speedup vs baseline: 1.7236x; 1.7236x over previous
#include <cuda_runtime.h>

// Problem constants (fixed by the reference)
#define KK   27
#define RR   50000
#define CIN  64
#define COUT 64
#define NOUT 150000

#define TILE 128      // rules per block
#define XPAD 132      // xs row stride in floats (16B-aligned rows, conflict-free pattern)

typedef unsigned long long ull;

// ---- packed f32x2 helpers -------------------------------------------------
__device__ __forceinline__ ull pk2(float lo, float hi) {
    ull r; asm("mov.b64 %0, {%1, %2};" : "=l"(r) : "f"(lo), "f"(hi)); return r;
}
__device__ __forceinline__ void upk2(ull v, float& lo, float& hi) {
    asm("mov.b64 {%0, %1}, %2;" : "=f"(lo), "=f"(hi) : "l"(v));
}
__device__ __forceinline__ ull fma2(ull a, ull b, ull c) {
    ull d; asm("fma.rn.f32x2 %0, %1, %2, %3;" : "=l"(d) : "l"(a), "l"(b), "l"(c)); return d;
}
// vectorized global reduction (PTX ISA 8.1+, sm_90+)
__device__ __forceinline__ void red4(float* p, float a, float b, float c, float d) {
    asm volatile("red.global.add.v4.f32 [%0], {%1, %2, %3, %4};"
                 :: "l"(p), "f"(a), "f"(b), "f"(c), "f"(d) : "memory");
}

// ---- out = bias broadcast --------------------------------------------------
__global__ void init_out_kernel(float4* __restrict__ out4, const float4* __restrict__ bias4) {
    int i = blockIdx.x * blockDim.x + threadIdx.x;
    if (i < NOUT * (COUT / 4)) {
        out4[i] = bias4[i & (COUT / 4 - 1)];
    }
}

// ---- main: per-offset tiled gather -> register GEMM -> red.v4 scatter ------
// smem layout (dynamic):
//   float wsm[CIN*COUT]  : W[k] plain float4 layout   = 16384 B
//   float xs[CIN*XPAD]   : gathered x, transposed     = 33792 B
//   int   ism[TILE], osm[TILE]                         = 1024 B
extern "C" __global__ void __launch_bounds__(128, 4)
sparse_conv_kernel(const float* __restrict__ x,
                   const float* __restrict__ w,
                   const int*   __restrict__ in_idx,
                   const int*   __restrict__ out_idx,
                   float*       __restrict__ out)
{
    extern __shared__ char smem_raw[];
    float* wsm = (float*)smem_raw;                                   // 16384 B
    float* xs  = (float*)(smem_raw + CIN * COUT * sizeof(float));    // 33792 B
    int*   ism = (int*)(smem_raw + CIN * COUT * sizeof(float)
                                 + CIN * XPAD * sizeof(float));
    int*   osm = ism + TILE;

    const int k     = blockIdx.y;
    const int rbase = blockIdx.x * TILE;
    const int tid   = threadIdx.x;

    // ---- stage W[k] (plain copy, float4) ----
    {
        const float4* wk4  = (const float4*)(w + k * CIN * COUT);
        float4*       wsm4 = (float4*)wsm;
        #pragma unroll
        for (int i = tid; i < CIN * COUT / 4; i += 128) wsm4[i] = wk4[i];
    }

    // ---- stage rule indices (thread = rule) ----
    {
        bool v = (rbase + tid) < RR;
        int rr = k * RR + rbase + tid;
        ism[tid] = v ? in_idx[rr]  : -1;
        osm[tid] = v ? out_idx[rr] : -1;
    }
    __syncthreads();

    // ---- gather x row for THIS thread's rule, transpose into xs[c][r] ----
    // STS pattern: per chunk q, all 128 threads write channel (4q+j) at column tid
    // -> consecutive lanes hit consecutive banks: conflict-free.
    {
        int gi = ism[tid];
        const float4* xrow = (const float4*)x + (long)gi * (CIN / 4);
        #pragma unroll
        for (int q = 0; q < CIN / 4; q++) {
            float4 v = make_float4(0.f, 0.f, 0.f, 0.f);
            if (gi >= 0) v = xrow[q];
            xs[(q * 4 + 0) * XPAD + tid] = v.x;
            xs[(q * 4 + 1) * XPAD + tid] = v.y;
            xs[(q * 4 + 2) * XPAD + tid] = v.z;
            xs[(q * 4 + 3) * XPAD + tid] = v.w;
        }
    }
    __syncthreads();

    // ---- register-blocked GEMM: 8 rules x 8 channels per thread ----
    // tx in [0,8): channels {4tx..4tx+3} and {32+4tx..32+4tx+3}
    //   (split halves so the two W LDS.128s are each conflict-free)
    // ty in [0,16): rules {8ty..8ty+7}, packed as 4 f32x2 pairs
    const int tx = tid & 7;
    const int ty = tid >> 3;
    const int nA = 4 * tx;          // channel group A base
    const int nB = 32 + 4 * tx;     // channel group B base
    const int rb = 8 * ty;          // rule base

    ull acc[4][8];                  // [rule_pair][channel j: 0-3=A, 4-7=B]
    #pragma unroll
    for (int i = 0; i < 4; i++)
        #pragma unroll
        for (int j = 0; j < 8; j++) acc[i][j] = pk2(0.f, 0.f);

    const float*  xc = xs + rb;
    const float4* wA = (const float4*)wsm + tx;       // chunk tx      (quads 0..7)
    const float4* wB = (const float4*)wsm + 8 + tx;   // chunk 8+tx    (quads 0..7)

    #pragma unroll 2
    for (int c = 0; c < CIN; c++) {
        // 8 rules' x values: 4 f32x2 pairs via two LDS.128 (1 wavefront each)
        ulonglong2 xa = *(const ulonglong2*)(xc);
        ulonglong2 xb = *(const ulonglong2*)(xc + 4);
        // 8 channels' W: two LDS.128, duplicated to pairs in registers
        float4 w0 = *wA;
        float4 w1 = *wB;
        ull wd0 = pk2(w0.x, w0.x), wd1 = pk2(w0.y, w0.y);
        ull wd2 = pk2(w0.z, w0.z), wd3 = pk2(w0.w, w0.w);
        ull wd4 = pk2(w1.x, w1.x), wd5 = pk2(w1.y, w1.y);
        ull wd6 = pk2(w1.z, w1.z), wd7 = pk2(w1.w, w1.w);

        acc[0][0] = fma2(xa.x, wd0, acc[0][0]);
        acc[0][1] = fma2(xa.x, wd1, acc[0][1]);
        acc[0][2] = fma2(xa.x, wd2, acc[0][2]);
        acc[0][3] = fma2(xa.x, wd3, acc[0][3]);
        acc[0][4] = fma2(xa.x, wd4, acc[0][4]);
        acc[0][5] = fma2(xa.x, wd5, acc[0][5]);
        acc[0][6] = fma2(xa.x, wd6, acc[0][6]);
        acc[0][7] = fma2(xa.x, wd7, acc[0][7]);

        acc[1][0] = fma2(xa.y, wd0, acc[1][0]);
        acc[1][1] = fma2(xa.y, wd1, acc[1][1]);
        acc[1][2] = fma2(xa.y, wd2, acc[1][2]);
        acc[1][3] = fma2(xa.y, wd3, acc[1][3]);
        acc[1][4] = fma2(xa.y, wd4, acc[1][4]);
        acc[1][5] = fma2(xa.y, wd5, acc[1][5]);
        acc[1][6] = fma2(xa.y, wd6, acc[1][6]);
        acc[1][7] = fma2(xa.y, wd7, acc[1][7]);

        acc[2][0] = fma2(xb.x, wd0, acc[2][0]);
        acc[2][1] = fma2(xb.x, wd1, acc[2][1]);
        acc[2][2] = fma2(xb.x, wd2, acc[2][2]);
        acc[2][3] = fma2(xb.x, wd3, acc[2][3]);
        acc[2][4] = fma2(xb.x, wd4, acc[2][4]);
        acc[2][5] = fma2(xb.x, wd5, acc[2][5]);
        acc[2][6] = fma2(xb.x, wd6, acc[2][6]);
        acc[2][7] = fma2(xb.x, wd7, acc[2][7]);

        acc[3][0] = fma2(xb.y, wd0, acc[3][0]);
        acc[3][1] = fma2(xb.y, wd1, acc[3][1]);
        acc[3][2] = fma2(xb.y, wd2, acc[3][2]);
        acc[3][3] = fma2(xb.y, wd3, acc[3][3]);
        acc[3][4] = fma2(xb.y, wd4, acc[3][4]);
        acc[3][5] = fma2(xb.y, wd5, acc[3][5]);
        acc[3][6] = fma2(xb.y, wd6, acc[3][6]);
        acc[3][7] = fma2(xb.y, wd7, acc[3][7]);

        xc += XPAD;
        wA += 16;   // next c row (64 floats = 16 float4)
        wB += 16;
    }

    // ---- scatter-add: red.global.add.v4.f32, 2 channel groups per rule ----
    #pragma unroll
    for (int p = 0; p < 4; p++) {
        float lo[8], hi[8];
        #pragma unroll
        for (int j = 0; j < 8; j++) upk2(acc[p][j], lo[j], hi[j]);

        int o0 = osm[rb + 2 * p];
        if (o0 >= 0) {
            float* base = out + (long)o0 * COUT;
            red4(base + nA, lo[0], lo[1], lo[2], lo[3]);
            red4(base + nB, lo[4], lo[5], lo[6], lo[7]);
        }
        int o1 = osm[rb + 2 * p + 1];
        if (o1 >= 0) {
            float* base = out + (long)o1 * COUT;
            red4(base + nA, hi[0], hi[1], hi[2], hi[3]);
            red4(base + nB, hi[4], hi[5], hi[6], hi[7]);
        }
    }
}

extern "C" void kernel_launch(void* const* d_in, const int* in_sizes, int n_in,
                              void* d_out, int out_size)
{
    const float* x       = (const float*)d_in[0];
    const float* w       = (const float*)d_in[1];
    const float* bias    = (const float*)d_in[2];
    const int*   in_idx  = (const int*)d_in[3];
    const int*   out_idx = (const int*)d_in[4];
    float*       out     = (float*)d_out;

    // 1) out = bias (broadcast); out is poisoned before timing
    {
        int n4 = NOUT * (COUT / 4);
        init_out_kernel<<<(n4 + 255) / 256, 256>>>((float4*)out, (const float4*)bias);
    }

    // 2) tiled gather/GEMM/scatter
    size_t smem = (size_t)CIN * COUT * sizeof(float)    // 16384
                + (size_t)CIN * XPAD * sizeof(float)    // 33792
                + 2 * TILE * sizeof(int);               // 1024
    cudaFuncSetAttribute(sparse_conv_kernel,
                         cudaFuncAttributeMaxDynamicSharedMemorySize, (int)smem);
    dim3 grid((RR + TILE - 1) / TILE, KK);
    sparse_conv_kernel<<<grid, 128, smem>>>(x, w, in_idx, out_idx, out);
}

// round 4
// speedup vs baseline: 2.0709x; 1.2015x over previous
#include <cuda_runtime.h>
#include <cuda_bf16.h>
#include <cstdint>

// Problem constants
#define KK   27
#define RR   50000
#define CIN  64
#define COUT 64
#define NIN  150000
#define NOUT 150000

#define TILE      128
#define NTILES    ((RR + TILE - 1) / TILE)               // 391
#define TPB_TILES 7
#define NBX       ((NTILES + TPB_TILES - 1) / TPB_TILES) // 56

// SMEM layout (byte offsets)
#define OFF_WH  0u
#define OFF_WL  8192u
#define OFF_AH  16384u
#define OFF_AL  32768u
#define OFF_OSM 49152u
#define SMEM_BYTES 49664

// ---- global scratch ----------------------------------------------------------
// xsplit[row] = 128 bf16: [hi(64) | lo(64)], 256B per row
__device__ __align__(16) unsigned short g_xsplit[(size_t)NIN * 128];
// wsplit[k] = wh tile (64 rows x 128B, SW128-preswizzled, cout-permuted) then wl
__device__ __align__(16) unsigned short g_wsplit[(size_t)KK * 8192];

// ---- helpers -------------------------------------------------------------------
__device__ __forceinline__ uint32_t smem_u32(const void* p) {
    uint32_t a;
    asm("{ .reg .u64 t; cvta.to.shared.u64 t, %1; cvt.u32.u64 %0, t; }" : "=r"(a) : "l"(p));
    return a;
}
__device__ __forceinline__ void ldm4(uint32_t addr, uint32_t& r0, uint32_t& r1,
                                     uint32_t& r2, uint32_t& r3) {
    asm volatile("ldmatrix.sync.aligned.m8n8.x4.shared.b16 {%0,%1,%2,%3}, [%4];"
                 : "=r"(r0), "=r"(r1), "=r"(r2), "=r"(r3) : "r"(addr));
}
__device__ __forceinline__ void mma_bf16(float4& d,
                                         uint32_t a0, uint32_t a1, uint32_t a2, uint32_t a3,
                                         uint32_t b0, uint32_t b1) {
    asm volatile("mma.sync.aligned.m16n8k16.row.col.f32.bf16.bf16.f32 "
                 "{%0,%1,%2,%3}, {%4,%5,%6,%7}, {%8,%9}, {%0,%1,%2,%3};"
                 : "+f"(d.x), "+f"(d.y), "+f"(d.z), "+f"(d.w)
                 : "r"(a0), "r"(a1), "r"(a2), "r"(a3), "r"(b0), "r"(b1));
}
__device__ __forceinline__ void red4(float* p, float a, float b, float c, float d) {
    asm volatile("red.global.add.v4.f32 [%0], {%1, %2, %3, %4};"
                 :: "l"(p), "f"(a), "f"(b), "f"(c), "f"(d) : "memory");
}
__device__ __forceinline__ void split_bf16(float v, unsigned short& h, unsigned short& l) {
    __nv_bfloat16 bh = __float2bfloat16(v);
    float fh = __bfloat162float(bh);
    __nv_bfloat16 bl = __float2bfloat16(v - fh);
    h = *reinterpret_cast<unsigned short*>(&bh);
    l = *reinterpret_cast<unsigned short*>(&bl);
}

// ---- precompute: split x into hi/lo bf16 table ---------------------------------
__global__ void split_x_kernel(const float* __restrict__ x) {
    int t = blockIdx.x * blockDim.x + threadIdx.x;
    if (t >= NIN * 8) return;
    int row = t >> 3, c8 = t & 7;
    const float4* p = (const float4*)(x + (size_t)row * 64 + c8 * 8);
    float4 a = p[0], b = p[1];
    float v[8] = {a.x, a.y, a.z, a.w, b.x, b.y, b.z, b.w};
    unsigned short hi[8], lo[8];
    #pragma unroll
    for (int j = 0; j < 8; j++) split_bf16(v[j], hi[j], lo[j]);
    *(uint4*)(g_xsplit + (size_t)row * 128 + c8 * 8)      = *(uint4*)hi;
    *(uint4*)(g_xsplit + (size_t)row * 128 + 64 + c8 * 8) = *(uint4*)lo;
}

// ---- precompute: split W, permute cout rows, pre-swizzle SW128 ------------------
// B tile storage: row r = cout-permuted, 64 bf16 cin per row (128B).
// Permutation: for cout o: f = 2*(o>>4) + (o&1); g = (o>>1)&7; r = g*8 + f.
// This makes each mma lane's d-frag cover 16 consecutive couts.
__global__ void split_w_kernel(const float* __restrict__ w) {
    int t = blockIdx.x * blockDim.x + threadIdx.x;
    if (t >= KK * CIN * COUT) return;
    int k = t / 4096, rem = t - k * 4096;
    int c = rem >> 6, o = rem & 63;              // w[k][c][o]
    unsigned short h, l;
    split_bf16(w[t], h, l);
    int r = ((o >> 1) & 7) * 8 + 2 * (o >> 4) + (o & 1);
    uint32_t off = (uint32_t)r * 128 + (uint32_t)c * 2;
    uint32_t sw  = off ^ ((off >> 3) & 0x70);
    g_wsplit[(size_t)k * 8192 + (sw >> 1)]        = h;
    g_wsplit[(size_t)k * 8192 + 4096 + (sw >> 1)] = l;
}

// ---- out = bias broadcast --------------------------------------------------------
__global__ void init_out_kernel(float4* __restrict__ out4, const float4* __restrict__ bias4) {
    int i = blockIdx.x * blockDim.x + threadIdx.x;
    if (i < NOUT * (COUT / 4)) out4[i] = bias4[i & (COUT / 4 - 1)];
}

// ---- main: gather -> mma.sync bf16-split GEMM -> red.v4 scatter ------------------
extern "C" __global__ void __launch_bounds__(256, 2)
sparse_mma_kernel(const int* __restrict__ in_idx,
                  const int* __restrict__ out_idx,
                  float*     __restrict__ out)
{
    extern __shared__ __align__(1024) char smem[];
    const uint32_t sbase = smem_u32(smem);
    const int tid  = threadIdx.x;
    const int lane = tid & 31;
    const int wrp  = tid >> 5;      // 0..7
    const int k    = blockIdx.y;
    int* osm = (int*)(smem + OFF_OSM);

    // stage W (pre-split, pre-permuted, pre-swizzled): straight 16KB copy
    {
        const uint4* wg  = (const uint4*)(g_wsplit + (size_t)k * 8192);
        uint4*       wsm = (uint4*)(smem + OFF_WH);
        #pragma unroll
        for (int i = tid; i < 1024; i += 256) wsm[i] = wg[i];
    }

    // gather-phase constants
    const int rl   = tid & 127;               // rule slot
    const int half = tid >> 7;                // 0: hi, 1: lo
    const uint32_t abase_st = (half ? OFF_AL : OFF_AH);

    // ldmatrix A address: row = 16*wrp + (lane&15); col per kstep
    const int arow = 16 * wrp + (lane & 15);
    const uint32_t a_xor  = (uint32_t)((arow & 7) << 4);
    const uint32_t a_rbh  = sbase + OFF_AH + (uint32_t)arow * 128;
    const uint32_t a_rbl  = sbase + OFF_AL + (uint32_t)arow * 128;
    const uint32_t a_kofs = (uint32_t)(((lane >> 4) & 1) * 16);

    // ldmatrix B address: x4 #p covers ngroups {2p, 2p+1}
    const uint32_t b_xor  = (uint32_t)((lane & 7) << 4);
    const uint32_t b_kofs = (uint32_t)(((lane >> 3) & 1) * 16);
    uint32_t b_rb[4];
    #pragma unroll
    for (int p = 0; p < 4; p++)
        b_rb[p] = (uint32_t)(((2 * p + (lane >> 4)) * 8 + (lane & 7)) * 128);

    // epilogue constants
    const int tq = lane & 3;
    const int m1 = 16 * wrp + (lane >> 2);    // 0..127 (row within tile)

    for (int i = 0; i < TPB_TILES; i++) {
        int t = blockIdx.x * TPB_TILES + i;
        if (t >= NTILES) break;
        int rg = t * TILE + rl;

        // ---- gather: rule row (hi or lo half) -> swizzled STS.128 ----
        if (tid < 128) osm[tid] = (rg < RR) ? out_idx[k * RR + rg] : -1;
        if (rg < RR) {
            int gi = in_idx[k * RR + rg];
            const uint4* src = (const uint4*)(g_xsplit + (size_t)gi * 128 + half * 64);
            #pragma unroll
            for (int c = 0; c < 8; c++) {
                uint32_t off = (uint32_t)rl * 128 + c * 16;
                uint32_t sw  = off ^ ((off >> 3) & 0x70);
                *(uint4*)(smem + abase_st + sw) = src[c];
            }
        }
        __syncthreads();

        const int o1 = osm[m1];
        const int o2 = osm[m1 + 8];

        // ---- MMA: 3-term split accumulate in registers ----
        float4 acc[8];
        #pragma unroll
        for (int g = 0; g < 8; g++) acc[g] = make_float4(0.f, 0.f, 0.f, 0.f);

        #pragma unroll
        for (int ks = 0; ks < 4; ks++) {
            uint32_t cola = (uint32_t)(32 * ks) + a_kofs;
            uint32_t ah0, ah1, ah2, ah3, al0, al1, al2, al3;
            ldm4(a_rbh + (cola ^ a_xor), ah0, ah1, ah2, ah3);
            ldm4(a_rbl + (cola ^ a_xor), al0, al1, al2, al3);

            uint32_t colb = (uint32_t)(32 * ks) + b_kofs;
            uint32_t bh[16];
            #pragma unroll
            for (int p = 0; p < 4; p++)
                ldm4(sbase + OFF_WH + b_rb[p] + (colb ^ b_xor),
                     bh[4 * p], bh[4 * p + 1], bh[4 * p + 2], bh[4 * p + 3]);

            #pragma unroll
            for (int g = 0; g < 8; g++)
                mma_bf16(acc[g], ah0, ah1, ah2, ah3, bh[2 * g], bh[2 * g + 1]);
            #pragma unroll
            for (int g = 0; g < 8; g++)
                mma_bf16(acc[g], al0, al1, al2, al3, bh[2 * g], bh[2 * g + 1]);

            uint32_t bl[16];
            #pragma unroll
            for (int p = 0; p < 4; p++)
                ldm4(sbase + OFF_WL + b_rb[p] + (colb ^ b_xor),
                     bl[4 * p], bl[4 * p + 1], bl[4 * p + 2], bl[4 * p + 3]);

            #pragma unroll
            for (int g = 0; g < 8; g++)
                mma_bf16(acc[g], ah0, ah1, ah2, ah3, bl[2 * g], bl[2 * g + 1]);
        }
        __syncthreads();   // A/W smem reads done; safe for next tile's STS

        // ---- scatter: 16 consecutive couts per lane per row (perm trick) ----
        if (o1 >= 0) {
            float* b = out + (size_t)o1 * COUT + 16 * tq;
            #pragma unroll
            for (int q = 0; q < 4; q++)
                red4(b + 4 * q, acc[2 * q].x, acc[2 * q].y,
                                acc[2 * q + 1].x, acc[2 * q + 1].y);
        }
        if (o2 >= 0) {
            float* b = out + (size_t)o2 * COUT + 16 * tq;
            #pragma unroll
            for (int q = 0; q < 4; q++)
                red4(b + 4 * q, acc[2 * q].z, acc[2 * q].w,
                                acc[2 * q + 1].z, acc[2 * q + 1].w);
        }
    }
}

extern "C" void kernel_launch(void* const* d_in, const int* in_sizes, int n_in,
                              void* d_out, int out_size)
{
    const float* x       = (const float*)d_in[0];
    const float* w       = (const float*)d_in[1];
    const float* bias    = (const float*)d_in[2];
    const int*   in_idx  = (const int*)d_in[3];
    const int*   out_idx = (const int*)d_in[4];
    float*       out     = (float*)d_out;

    split_x_kernel<<<(NIN * 8 + 255) / 256, 256>>>(x);
    split_w_kernel<<<(KK * CIN * COUT + 255) / 256, 256>>>(w);

    {
        int n4 = NOUT * (COUT / 4);
        init_out_kernel<<<(n4 + 255) / 256, 256>>>((float4*)out, (const float4*)bias);
    }

    cudaFuncSetAttribute(sparse_mma_kernel,
                         cudaFuncAttributeMaxDynamicSharedMemorySize, SMEM_BYTES);
    dim3 grid(NBX, KK);
    sparse_mma_kernel<<<grid, 256, SMEM_BYTES>>>(in_idx, out_idx, out);
}

// round 5
// speedup vs baseline: 2.1724x; 1.0490x over previous
#include <cuda_runtime.h>
#include <cuda_bf16.h>
#include <cstdint>

// Problem constants
#define KK   27
#define RR   50000
#define CIN  64
#define COUT 64
#define NIN  150000
#define NOUT 150000

#define TILE    128
#define NTILES  ((RR + TILE - 1) / TILE)      // 391
#define NPAIRS  ((NTILES + 1) / 2)            // 196
#define PPB     4                             // tile-pairs per block
#define NBX     ((NPAIRS + PPB - 1) / PPB)    // 49

// SMEM layout (byte offsets): W(hi|lo) 16K, A buffers 4x16K, osm 1K
#define OFF_WH  0u
#define OFF_WL  8192u
#define OFF_A   16384u       // AH(tt) = OFF_A + tt*32768 ; AL(tt) = +16384
#define OFF_OSM 81920u
#define SMEM_BYTES 82944

// ---- global scratch ----------------------------------------------------------
__device__ __align__(16) unsigned short g_xsplit[(size_t)NIN * 128];   // [hi64|lo64]
__device__ __align__(16) unsigned short g_wsplit[(size_t)KK * 8192];   // wh|wl swizzled

// ---- helpers -------------------------------------------------------------------
__device__ __forceinline__ uint32_t smem_u32(const void* p) {
    uint32_t a;
    asm("{ .reg .u64 t; cvta.to.shared.u64 t, %1; cvt.u32.u64 %0, t; }" : "=r"(a) : "l"(p));
    return a;
}
__device__ __forceinline__ void ldm4(uint32_t addr, uint32_t& r0, uint32_t& r1,
                                     uint32_t& r2, uint32_t& r3) {
    asm volatile("ldmatrix.sync.aligned.m8n8.x4.shared.b16 {%0,%1,%2,%3}, [%4];"
                 : "=r"(r0), "=r"(r1), "=r"(r2), "=r"(r3) : "r"(addr));
}
__device__ __forceinline__ void mma_bf16(float4& d,
                                         uint32_t a0, uint32_t a1, uint32_t a2, uint32_t a3,
                                         uint32_t b0, uint32_t b1) {
    asm volatile("mma.sync.aligned.m16n8k16.row.col.f32.bf16.bf16.f32 "
                 "{%0,%1,%2,%3}, {%4,%5,%6,%7}, {%8,%9}, {%0,%1,%2,%3};"
                 : "+f"(d.x), "+f"(d.y), "+f"(d.z), "+f"(d.w)
                 : "r"(a0), "r"(a1), "r"(a2), "r"(a3), "r"(b0), "r"(b1));
}
__device__ __forceinline__ void red4(float* p, float a, float b, float c, float d) {
    asm volatile("red.global.add.v4.f32 [%0], {%1, %2, %3, %4};"
                 :: "l"(p), "f"(a), "f"(b), "f"(c), "f"(d) : "memory");
}
__device__ __forceinline__ void split_bf16(float v, unsigned short& h, unsigned short& l) {
    __nv_bfloat16 bh = __float2bfloat16(v);
    float fh = __bfloat162float(bh);
    __nv_bfloat16 bl = __float2bfloat16(v - fh);
    h = *reinterpret_cast<unsigned short*>(&bh);
    l = *reinterpret_cast<unsigned short*>(&bl);
}

// ---- precompute: split x into hi/lo bf16 table ---------------------------------
__global__ void split_x_kernel(const float* __restrict__ x) {
    int t = blockIdx.x * blockDim.x + threadIdx.x;
    if (t >= NIN * 8) return;
    int row = t >> 3, c8 = t & 7;
    const float4* p = (const float4*)(x + (size_t)row * 64 + c8 * 8);
    float4 a = p[0], b = p[1];
    float v[8] = {a.x, a.y, a.z, a.w, b.x, b.y, b.z, b.w};
    unsigned short hi[8], lo[8];
    #pragma unroll
    for (int j = 0; j < 8; j++) split_bf16(v[j], hi[j], lo[j]);
    *(uint4*)(g_xsplit + (size_t)row * 128 + c8 * 8)      = *(uint4*)hi;
    *(uint4*)(g_xsplit + (size_t)row * 128 + 64 + c8 * 8) = *(uint4*)lo;
}

// ---- precompute: split W, permute cout rows, pre-swizzle SW128 ------------------
// Row permutation r = ((o>>1)&7)*8 + 2*(o>>4) + (o&1): each mma lane's d-frag
// covers 16 consecutive couts -> shuffle-free red.v4 epilogue.
__global__ void split_w_kernel(const float* __restrict__ w) {
    int t = blockIdx.x * blockDim.x + threadIdx.x;
    if (t >= KK * CIN * COUT) return;
    int k = t / 4096, rem = t - k * 4096;
    int c = rem >> 6, o = rem & 63;
    unsigned short h, l;
    split_bf16(w[t], h, l);
    int r = ((o >> 1) & 7) * 8 + 2 * (o >> 4) + (o & 1);
    uint32_t off = (uint32_t)r * 128 + (uint32_t)c * 2;
    uint32_t sw  = off ^ ((off >> 3) & 0x70);
    g_wsplit[(size_t)k * 8192 + (sw >> 1)]        = h;
    g_wsplit[(size_t)k * 8192 + 4096 + (sw >> 1)] = l;
}

// ---- out = bias broadcast --------------------------------------------------------
__global__ void init_out_kernel(float4* __restrict__ out4, const float4* __restrict__ bias4) {
    int i = blockIdx.x * blockDim.x + threadIdx.x;
    if (i < NOUT * (COUT / 4)) out4[i] = bias4[i & (COUT / 4 - 1)];
}

// ---- main: gather -> mma (2 tiles per B-fragment load) -> red.v4 scatter ---------
extern "C" __global__ void __launch_bounds__(256, 2)
sparse_mma_kernel(const int* __restrict__ in_idx,
                  const int* __restrict__ out_idx,
                  float*     __restrict__ out)
{
    extern __shared__ __align__(1024) char smem[];
    const uint32_t sbase = smem_u32(smem);
    const int tid  = threadIdx.x;
    const int lane = tid & 31;
    const int wrp  = tid >> 5;
    const int k    = blockIdx.y;
    int* osm = (int*)(smem + OFF_OSM);   // 256 entries (2 tiles)

    // stage W (pre-split, pre-permuted, pre-swizzled): 16KB copy
    {
        const uint4* wg  = (const uint4*)(g_wsplit + (size_t)k * 8192);
        uint4*       wsm = (uint4*)(smem + OFF_WH);
        #pragma unroll
        for (int i = tid; i < 1024; i += 256) wsm[i] = wg[i];
    }

    // gather constants: thread handles rule slot rl, hi or lo half
    const int rl   = tid & 127;
    const int half = tid >> 7;

    // ldmatrix A addressing: row = 16*wrp + (lane&15)
    const int arow = 16 * wrp + (lane & 15);
    const uint32_t a_xor  = (uint32_t)((arow & 7) << 4);
    const uint32_t a_row_bytes = (uint32_t)arow * 128;
    const uint32_t a_kofs = (uint32_t)(((lane >> 4) & 1) * 16);

    // ldmatrix B addressing: x4 #p covers ngroups {2p, 2p+1}
    const uint32_t b_xor  = (uint32_t)((lane & 7) << 4);
    const uint32_t b_kofs = (uint32_t)(((lane >> 3) & 1) * 16);
    uint32_t b_rb[4];
    #pragma unroll
    for (int p = 0; p < 4; p++)
        b_rb[p] = (uint32_t)(((2 * p + (lane >> 4)) * 8 + (lane & 7)) * 128);

    // epilogue constants
    const int tq = lane & 3;
    const int m1 = 16 * wrp + (lane >> 2);

    for (int i = 0; i < PPB; i++) {
        int pair = blockIdx.x * PPB + i;
        int t0 = pair * 2;
        if (t0 >= NTILES) break;

        // ---- gather 2 tiles: swizzled STS.128 of this thread's half-row ----
        #pragma unroll
        for (int tt = 0; tt < 2; tt++) {
            int rg = (t0 + tt) * TILE + rl;
            if (rg < RR) {
                int gi = in_idx[k * RR + rg];
                const uint4* src = (const uint4*)(g_xsplit + (size_t)gi * 128 + half * 64);
                uint32_t ab = OFF_A + (uint32_t)tt * 32768u + (uint32_t)half * 16384u;
                #pragma unroll
                for (int c = 0; c < 8; c++) {
                    uint32_t off = (uint32_t)rl * 128 + c * 16;
                    uint32_t sw  = off ^ ((off >> 3) & 0x70);
                    *(uint4*)(smem + ab + sw) = src[c];
                }
            }
        }
        {   // osm: tid<128 -> tile0, tid>=128 -> tile1
            int rg = (t0 + half) * TILE + rl;
            osm[tid] = (rg < RR) ? out_idx[k * RR + rg] : -1;
        }
        __syncthreads();

        // ---- MMA: per kstep load B once, apply to both tiles ----
        float4 acc[2][8];
        #pragma unroll
        for (int tt = 0; tt < 2; tt++)
            #pragma unroll
            for (int g = 0; g < 8; g++) acc[tt][g] = make_float4(0.f, 0.f, 0.f, 0.f);

        uint32_t Ah[2][4];   // kept across bh->bl phases

        #pragma unroll
        for (int ks = 0; ks < 4; ks++) {
            uint32_t cola = (uint32_t)(32 * ks) + a_kofs;
            uint32_t colb = (uint32_t)(32 * ks) + b_kofs;

            uint32_t B[16];
            #pragma unroll
            for (int p = 0; p < 4; p++)
                ldm4(sbase + OFF_WH + b_rb[p] + (colb ^ b_xor),
                     B[4 * p], B[4 * p + 1], B[4 * p + 2], B[4 * p + 3]);

            #pragma unroll
            for (int tt = 0; tt < 2; tt++) {
                uint32_t ahb = sbase + OFF_A + (uint32_t)tt * 32768u + a_row_bytes;
                ldm4(ahb + (cola ^ a_xor), Ah[tt][0], Ah[tt][1], Ah[tt][2], Ah[tt][3]);
                uint32_t al0, al1, al2, al3;
                ldm4(ahb + 16384u + (cola ^ a_xor), al0, al1, al2, al3);
                #pragma unroll
                for (int g = 0; g < 8; g++)
                    mma_bf16(acc[tt][g], Ah[tt][0], Ah[tt][1], Ah[tt][2], Ah[tt][3],
                             B[2 * g], B[2 * g + 1]);
                #pragma unroll
                for (int g = 0; g < 8; g++)
                    mma_bf16(acc[tt][g], al0, al1, al2, al3, B[2 * g], B[2 * g + 1]);
            }

            #pragma unroll
            for (int p = 0; p < 4; p++)
                ldm4(sbase + OFF_WL + b_rb[p] + (colb ^ b_xor),
                     B[4 * p], B[4 * p + 1], B[4 * p + 2], B[4 * p + 3]);

            #pragma unroll
            for (int tt = 0; tt < 2; tt++)
                #pragma unroll
                for (int g = 0; g < 8; g++)
                    mma_bf16(acc[tt][g], Ah[tt][0], Ah[tt][1], Ah[tt][2], Ah[tt][3],
                             B[2 * g], B[2 * g + 1]);
        }
        __syncthreads();   // smem reads done before next pair's STS

        // ---- scatter: 16 consecutive couts per lane per row ----
        #pragma unroll
        for (int tt = 0; tt < 2; tt++) {
            int o1 = osm[tt * 128 + m1];
            int o2 = osm[tt * 128 + m1 + 8];
            if (o1 >= 0) {
                float* b = out + (size_t)o1 * COUT + 16 * tq;
                #pragma unroll
                for (int q = 0; q < 4; q++)
                    red4(b + 4 * q, acc[tt][2 * q].x, acc[tt][2 * q].y,
                                    acc[tt][2 * q + 1].x, acc[tt][2 * q + 1].y);
            }
            if (o2 >= 0) {
                float* b = out + (size_t)o2 * COUT + 16 * tq;
                #pragma unroll
                for (int q = 0; q < 4; q++)
                    red4(b + 4 * q, acc[tt][2 * q].z, acc[tt][2 * q].w,
                                    acc[tt][2 * q + 1].z, acc[tt][2 * q + 1].w);
            }
        }
    }
}

extern "C" void kernel_launch(void* const* d_in, const int* in_sizes, int n_in,
                              void* d_out, int out_size)
{
    const float* x       = (const float*)d_in[0];
    const float* w       = (const float*)d_in[1];
    const float* bias    = (const float*)d_in[2];
    const int*   in_idx  = (const int*)d_in[3];
    const int*   out_idx = (const int*)d_in[4];
    float*       out     = (float*)d_out;

    split_x_kernel<<<(NIN * 8 + 255) / 256, 256>>>(x);
    split_w_kernel<<<(KK * CIN * COUT + 255) / 256, 256>>>(w);

    {
        int n4 = NOUT * (COUT / 4);
        init_out_kernel<<<(n4 + 255) / 256, 256>>>((float4*)out, (const float4*)bias);
    }

    cudaFuncSetAttribute(sparse_mma_kernel,
                         cudaFuncAttributeMaxDynamicSharedMemorySize, SMEM_BYTES);
    dim3 grid(NBX, KK);
    sparse_mma_kernel<<<grid, 256, SMEM_BYTES>>>(in_idx, out_idx, out);
}